// round 5
// baseline (speedup 1.0000x reference)
#include <cuda_runtime.h>
#include <cuda_bf16.h>
#include <math.h>
#include <cstdint>

#define NB   128
#define CIN  3
#define DIN  18
#define HIN  34
#define WIN  34
#define HW   (HIN * WIN)
#define COUT 16
#define DOUT 16
#define HOUT 32
#define WOUT 32

#define KPAD    112          // 27 taps * 4 (kw padded to 4) + 4 extra zero
#define NKS     7            // 112 / 16 k-steps
#define BSTRIDE 120          // B row stride in bf16
#define SLAB_P  (9 * 1156 + 16)   // pair-slab positions (+ overrun pad)

// dynamic smem (bytes): hipair u32[SLAB_P] | lopair u32[SLAB_P] | Bhi/Blo bf16
#define DSMEM_BYTES (SLAB_P * 4 * 2 + 2 * COUT * BSTRIDE * 2)

// Scratch (device globals: allocation-free per harness rules)
__device__ float g_y[(size_t)NB * COUT * DOUT * HOUT * WOUT];   // 134 MB conv output
__device__ float g_part[NB * COUT * DOUT * 2];                  // per-(b,c,d) sum/sumsq

// ---------------- mma.sync m16n8k16 bf16 (classic tensor path) ----------------
__device__ __forceinline__ void mma_bf16(float* c,
                                         uint32_t a0, uint32_t a1, uint32_t a2, uint32_t a3,
                                         uint32_t b0, uint32_t b1) {
    asm volatile(
        "mma.sync.aligned.m16n8k16.row.col.f32.bf16.bf16.f32 "
        "{%0,%1,%2,%3}, {%4,%5,%6,%7}, {%8,%9}, {%0,%1,%2,%3};"
        : "+f"(c[0]), "+f"(c[1]), "+f"(c[2]), "+f"(c[3])
        : "r"(a0), "r"(a1), "r"(a2), "r"(a3), "r"(b0), "r"(b1));
}

// ---------------------------------------------------------------------------
// Kernel 1: conv3d + bias + channel-mult via mma.sync bf16 hi/lo implicit GEMM.
// Grid (DOUT, NB), 256 threads = 8 warps, 2 CTAs/SM.
// A fragments come from pre-converted bf16x2 PAIR slabs: 1 LDS.32 per frag reg.
// ---------------------------------------------------------------------------
__global__ void __launch_bounds__(256, 2) conv_kernel(
    const float* __restrict__ x,
    const float* __restrict__ cw,
    const float* __restrict__ cb,
    const float* __restrict__ mult)
{
    extern __shared__ uint32_t smu[];
    uint32_t*       hipair = smu;
    uint32_t*       lopair = smu + SLAB_P;
    __nv_bfloat16*  Bhi    = (__nv_bfloat16*)(smu + 2 * SLAB_P);
    __nv_bfloat16*  Blo    = Bhi + COUT * BSTRIDE;

    __shared__ float sbm[2 * COUT];
    __shared__ float sred[8][COUT][2];

    const int tid = threadIdx.x;
    const int wid = tid >> 5;
    const int lid = tid & 31;
    const int d   = blockIdx.x;
    const int b   = blockIdx.y;

    // ---- build bf16x2 pair slabs straight from gmem (convert ONCE) ----
    const float* xb = x + (size_t)b * (CIN * DIN * HW);
    for (int i = tid; i < 9 * 1156; i += 256) {
        const int plane = i / 1156;              // ci*3 + kd
        const int pos   = i - plane * 1156;
        const int ci    = plane / 3;
        const int kd    = plane - ci * 3;
        const float* src = xb + ci * (DIN * HW) + (d + kd) * HW + pos;
        const float f0 = __ldg(src);
        const float f1 = (pos < 1155) ? __ldg(src + 1) : 0.0f;
        __nv_bfloat162 h = __floats2bfloat162_rn(f0, f1);
        hipair[i] = *reinterpret_cast<uint32_t*>(&h);
        const float r0 = f0 - __bfloat162float(h.x);
        const float r1 = f1 - __bfloat162float(h.y);
        __nv_bfloat162 l = __floats2bfloat162_rn(r0, r1);
        lopair[i] = *reinterpret_cast<uint32_t*>(&l);
    }
    // ---- build B hi/lo: B[c][k'] ; k' = tap*4 + kw (kw<3 real, else 0) ----
    for (int i = tid; i < COUT * BSTRIDE; i += 256) {
        const int c = i / BSTRIDE;
        const int k = i - c * BSTRIDE;
        float wv = 0.0f;
        if (k < 108 && (k & 3) < 3) wv = cw[c * 81 + (k >> 2) * 3 + (k & 3)];
        __nv_bfloat16 h = __float2bfloat16(wv);
        Bhi[i] = h;
        Blo[i] = __float2bfloat16(wv - __bfloat162float(h));
    }
    if (tid < COUT) { sbm[tid] = cb[tid]; sbm[COUT + tid] = mult[tid]; }
    __syncthreads();

    // ---- per-lane A base offsets (pair-slab positions) per (kstep, slot) ----
    const int t4 = lid & 3;
    const int g  = lid >> 2;
    int abase[2 * NKS];
    #pragma unroll
    for (int ks = 0; ks < NKS; ks++) {
        #pragma unroll
        for (int slot = 0; slot < 2; slot++) {
            int k   = ks * 16 + t4 * 2 + slot * 8;
            int tap = k >> 2;
            if (tap > 26) tap = 0;               // padded k-range: B is zero there
            const int plane = tap / 3;
            const int kh    = tap - plane * 3;
            abase[ks * 2 + slot] = plane * 1156 + kh * 34 + (k & 3);
        }
    }

    // ---- hoist B fragments (constant across tiles) ----
    uint32_t Bf[NKS][8];
    #pragma unroll
    for (int ks = 0; ks < NKS; ks++) {
        const int bidx  = g * BSTRIDE + ks * 16 + t4 * 2;
        const int bidx2 = bidx + 8 * BSTRIDE;
        Bf[ks][0] = *(const uint32_t*)(Bhi + bidx);
        Bf[ks][1] = *(const uint32_t*)(Bhi + bidx + 8);
        Bf[ks][2] = *(const uint32_t*)(Blo + bidx);
        Bf[ks][3] = *(const uint32_t*)(Blo + bidx + 8);
        Bf[ks][4] = *(const uint32_t*)(Bhi + bidx2);
        Bf[ks][5] = *(const uint32_t*)(Bhi + bidx2 + 8);
        Bf[ks][6] = *(const uint32_t*)(Blo + bidx2);
        Bf[ks][7] = *(const uint32_t*)(Blo + bidx2 + 8);
    }

    const int h_lo = wid >> 1;                    // h = t*4 + h_lo
    const int w0   = (wid & 1) * 16 + g;

    // bias/mult for this thread's 4 channels: ch0, ch0+1, ch0+8, ch0+9
    const int ch0 = 2 * t4;
    float bm_b[4] = { sbm[ch0], sbm[ch0 + 1], sbm[ch0 + 8], sbm[ch0 + 9] };
    float bm_m[4] = { sbm[COUT + ch0], sbm[COUT + ch0 + 1],
                      sbm[COUT + ch0 + 8], sbm[COUT + ch0 + 9] };

    float s4[4] = {0.f, 0.f, 0.f, 0.f};
    float q4[4] = {0.f, 0.f, 0.f, 0.f};

    const size_t ybase = ((size_t)b * COUT * DOUT + d) << 10;

    for (int t = 0; t < 8; t++) {
        float acc0[4] = {0.f, 0.f, 0.f, 0.f};
        float acc1[4] = {0.f, 0.f, 0.f, 0.f};

        const int hw = (t * 4 + h_lo) * 34 + w0;

        #pragma unroll
        for (int ks = 0; ks < NKS; ks++) {
            const int p0 = abase[ks * 2 + 0] + hw;
            const int p1 = abase[ks * 2 + 1] + hw;
            const uint32_t ah0 = hipair[p0];
            const uint32_t ah1 = hipair[p0 + 8];
            const uint32_t ah2 = hipair[p1];
            const uint32_t ah3 = hipair[p1 + 8];
            const uint32_t al0 = lopair[p0];
            const uint32_t al1 = lopair[p0 + 8];
            const uint32_t al2 = lopair[p1];
            const uint32_t al3 = lopair[p1 + 8];

            mma_bf16(acc0, ah0, ah1, ah2, ah3, Bf[ks][0], Bf[ks][1]);
            mma_bf16(acc0, al0, al1, al2, al3, Bf[ks][0], Bf[ks][1]);
            mma_bf16(acc0, ah0, ah1, ah2, ah3, Bf[ks][2], Bf[ks][3]);
            mma_bf16(acc1, ah0, ah1, ah2, ah3, Bf[ks][4], Bf[ks][5]);
            mma_bf16(acc1, al0, al1, al2, al3, Bf[ks][4], Bf[ks][5]);
            mma_bf16(acc1, ah0, ah1, ah2, ah3, Bf[ks][6], Bf[ks][7]);
        }

        // epilogue: bias+mult, store y, accumulate stats
        const int rbase = t * 128 + wid * 16 + g;
        #pragma unroll
        for (int j = 0; j < 4; j++) {
            const int jc = j & 1;
            const int r  = rbase + ((j >> 1) << 3);
            {
                const float v = (acc0[j] + bm_b[jc]) * bm_m[jc];
                const int c = ch0 + jc;
                g_y[ybase + (size_t)c * (DOUT << 10) + r] = v;
                s4[jc] += v; q4[jc] += v * v;
            }
            {
                const float v = (acc1[j] + bm_b[2 + jc]) * bm_m[2 + jc];
                const int c = ch0 + 8 + jc;
                g_y[ybase + (size_t)c * (DOUT << 10) + r] = v;
                s4[2 + jc] += v; q4[2 + jc] += v * v;
            }
        }
    }

    // ---- stats reduction ----
    #pragma unroll
    for (int j = 0; j < 4; j++) {
        #pragma unroll
        for (int off = 16; off >= 4; off >>= 1) {
            s4[j] += __shfl_down_sync(0xffffffffu, s4[j], off);
            q4[j] += __shfl_down_sync(0xffffffffu, q4[j], off);
        }
    }
    if (lid < 4) {
        const int c0 = 2 * lid;
        sred[wid][c0][0]     = s4[0];  sred[wid][c0][1]     = q4[0];
        sred[wid][c0 + 1][0] = s4[1];  sred[wid][c0 + 1][1] = q4[1];
        sred[wid][c0 + 8][0] = s4[2];  sred[wid][c0 + 8][1] = q4[2];
        sred[wid][c0 + 9][0] = s4[3];  sred[wid][c0 + 9][1] = q4[3];
    }
    __syncthreads();
    if (tid < 32) {
        const int c = tid & 15, which = tid >> 4;
        float v = 0.f;
        #pragma unroll
        for (int wi = 0; wi < 8; wi++) v += sred[wi][c][which];
        g_part[((b * COUT + c) * DOUT + d) * 2 + which] = v;
    }
}

// ---------------------------------------------------------------------------
// Kernel 2: fold partials -> mean/rstd, normalize, clamp, mult, max over c.
// ---------------------------------------------------------------------------
__global__ void __launch_bounds__(256) norm_kernel(
    const float* __restrict__ mult,
    float* __restrict__ out)
{
    const int d   = blockIdx.x;
    const int b   = blockIdx.y;
    const int tid = threadIdx.x;

    __shared__ float smean[COUT], srs[COUT], smu[COUT];

    if (tid < COUT) {
        float s = 0.0f, q = 0.0f;
        #pragma unroll
        for (int dd = 0; dd < DOUT; dd++) {
            s += g_part[((b * COUT + tid) * DOUT + dd) * 2];
            q += g_part[((b * COUT + tid) * DOUT + dd) * 2 + 1];
        }
        const float invN = 1.0f / (float)(DOUT * HOUT * WOUT);
        const float mean = s * invN;
        const float var  = q * invN - mean * mean;
        smean[tid] = mean;
        srs[tid]   = rsqrtf(var + 1e-5f);
        smu[tid]   = mult[tid];
    }
    __syncthreads();

    const int h  = tid >> 3;
    const int w0 = (tid & 7) << 2;

    float m0 = -INFINITY, m1 = -INFINITY, m2 = -INFINITY, m3 = -INFINITY;

    #pragma unroll
    for (int c = 0; c < COUT; c++) {
        const float4 v = *(const float4*)&g_y[
            (((size_t)(b * COUT + c) * DOUT + d) << 10) + h * WOUT + w0];
        const float mean = smean[c];
        const float rs   = srs[c];
        const float mu   = smu[c];
        float r;
        r = fminf(fmaxf((v.x - mean) * rs, -1.0f), 1.0f) * mu; m0 = fmaxf(m0, r);
        r = fminf(fmaxf((v.y - mean) * rs, -1.0f), 1.0f) * mu; m1 = fmaxf(m1, r);
        r = fminf(fmaxf((v.z - mean) * rs, -1.0f), 1.0f) * mu; m2 = fmaxf(m2, r);
        r = fminf(fmaxf((v.w - mean) * rs, -1.0f), 1.0f) * mu; m3 = fmaxf(m3, r);
    }

    *(float4*)&out[(((size_t)b * DOUT + d) << 10) + h * WOUT + w0] =
        make_float4(m0, m1, m2, m3);
}

// ---------------------------------------------------------------------------
extern "C" void kernel_launch(void* const* d_in, const int* in_sizes, int n_in,
                              void* d_out, int out_size)
{
    const float* x    = (const float*)d_in[0];
    const float* cw   = (const float*)d_in[1];
    const float* cb   = (const float*)d_in[2];
    const float* mult = (const float*)d_in[3];
    float* out = (float*)d_out;

    cudaFuncSetAttribute(conv_kernel,
                         cudaFuncAttributeMaxDynamicSharedMemorySize,
                         DSMEM_BYTES);

    dim3 grid(DOUT, NB);
    conv_kernel<<<grid, 256, DSMEM_BYTES>>>(x, cw, cb, mult);
    norm_kernel<<<grid, 256>>>(mult, out);
}